// round 14
// baseline (speedup 1.0000x reference)
#include <cuda_runtime.h>
#include <math.h>
#include <stdint.h>

#define BB   2
#define SS   2048
#define DD   512
#define WW   64
#define MR   (BB*SS)     // 4096 rows

// Scratch (device globals — no allocation allowed)
__device__ float g_q[MR*DD];
__device__ float g_k[MR*DD];
__device__ float g_v[MR*DD];
__device__ float g_r[MR*DD];
__device__ float g_att[MR*DD];
__device__ float g_proj[MR*DD];

__device__ __forceinline__ uint32_t tf32r(float f) {
    uint32_t u; asm("cvt.rna.tf32.f32 %0, %1;" : "=r"(u) : "f"(f)); return u;
}

__device__ __forceinline__ void mma_tf32(float* c, const uint32_t* a, const uint32_t* b) {
    asm("mma.sync.aligned.m16n8k8.row.col.f32.tf32.tf32.f32 "
        "{%0,%1,%2,%3}, {%4,%5,%6,%7}, {%8,%9}, {%0,%1,%2,%3};"
        : "+f"(c[0]), "+f"(c[1]), "+f"(c[2]), "+f"(c[3])
        : "r"(a[0]), "r"(a[1]), "r"(a[2]), "r"(a[3]), "r"(b[0]), "r"(b[1]));
}

__device__ __forceinline__ void ldsm_x4(uint32_t* r, uint32_t addr) {
    asm volatile("ldmatrix.sync.aligned.m8n8.x4.shared.b16 {%0,%1,%2,%3}, [%4];"
                 : "=r"(r[0]), "=r"(r[1]), "=r"(r[2]), "=r"(r[3]) : "r"(addr));
}

// ===========================================================================
// tf32 tensor-core GEMM: C[4096,512] = A[4096,512] @ W[512,512] + bias
// CTA tile 128x128, BK=32, 128 threads (4 warps, warp tile 64x64).
// A fragments via ldmatrix.x4. (R13 body — best measured.)
// ===========================================================================
#define SKA 36
#define SKB 132

__device__ __forceinline__ void gemm_mma(const float* __restrict__ A,
                                         const float* __restrict__ W,
                                         const float* __restrict__ bias,
                                         float* __restrict__ C)
{
    __shared__ float As[128 * SKA];
    __shared__ float Bs[32 * SKB];

    const int tid  = threadIdx.x;
    const int lane = tid & 31;
    const int wid  = tid >> 5;
    const int g    = lane >> 2;
    const int tg   = lane & 3;
    const int m0   = blockIdx.y * 128;
    const int n0   = blockIdx.x * 128;
    const int wm   = (wid >> 1) * 64;
    const int wn   = (wid & 1) * 64;

    const int arow = tid >> 3;
    const int acol = (tid & 7) * 4;
    const int brow = tid >> 5;
    const int bcol = (tid & 31) * 4;

    const float* Ab = A + (m0 + arow) * DD + acol;
    const float* Wb = W + brow * DD + n0 + bcol;

    const uint32_t sAs = (uint32_t)__cvta_generic_to_shared(As);
    uint32_t ptrA[4];
#pragma unroll
    for (int mt = 0; mt < 4; mt++)
        ptrA[mt] = sAs + (((wm + mt * 16 + (lane & 15)) * SKA) + (lane >> 4) * 4) * 4;

    float4 pa[8], pb[8];
#pragma unroll
    for (int i = 0; i < 8; i++) {
        pa[i] = *(const float4*)(Ab + i * 16 * DD);
        pb[i] = *(const float4*)(Wb + i * 4 * DD);
    }

    float acc[4][8][4];
#pragma unroll
    for (int mt = 0; mt < 4; mt++)
#pragma unroll
        for (int nt = 0; nt < 8; nt++)
#pragma unroll
            for (int q = 0; q < 4; q++) acc[mt][nt][q] = 0.f;

    for (int ch = 0; ch < 16; ch++) {
        __syncthreads();
#pragma unroll
        for (int i = 0; i < 8; i++) {
            uint4 ua;
            ua.x = tf32r(pa[i].x); ua.y = tf32r(pa[i].y);
            ua.z = tf32r(pa[i].z); ua.w = tf32r(pa[i].w);
            *(uint4*)&As[(arow + 16 * i) * SKA + acol] = ua;
            uint4 ub;
            ub.x = tf32r(pb[i].x); ub.y = tf32r(pb[i].y);
            ub.z = tf32r(pb[i].z); ub.w = tf32r(pb[i].w);
            *(uint4*)&Bs[(brow + 4 * i) * SKB + bcol] = ub;
        }
        __syncthreads();

        if (ch < 15) {
            const float* Ab2 = Ab + (ch + 1) * 32;
            const float* Wb2 = Wb + (ch + 1) * 32 * DD;
#pragma unroll
            for (int i = 0; i < 8; i++) {
                pa[i] = *(const float4*)(Ab2 + i * 16 * DD);
                pb[i] = *(const float4*)(Wb2 + i * 4 * DD);
            }
        }

#pragma unroll
        for (int kk = 0; kk < 4; kk++) {
            const int kb = kk * 8;
            uint32_t af[4][4], bf[8][2];
#pragma unroll
            for (int mt = 0; mt < 4; mt++)
                ldsm_x4(af[mt], ptrA[mt] + kb * 4);
#pragma unroll
            for (int nt = 0; nt < 8; nt++) {
                const int n = wn + nt * 8 + g;
                bf[nt][0] = __float_as_uint(Bs[(kb + tg) * SKB + n]);
                bf[nt][1] = __float_as_uint(Bs[(kb + tg + 4) * SKB + n]);
            }
#pragma unroll
            for (int mt = 0; mt < 4; mt++)
#pragma unroll
                for (int nt = 0; nt < 8; nt++)
                    mma_tf32(acc[mt][nt], af[mt], bf[nt]);
        }
    }

#pragma unroll
    for (int nt = 0; nt < 8; nt++) {
        const int n = n0 + wn + nt * 8 + 2 * tg;
        const float2 bb = *(const float2*)&bias[n];
#pragma unroll
        for (int mt = 0; mt < 4; mt++) {
            const int m = m0 + wm + mt * 16 + g;
            float2 v0 = make_float2(acc[mt][nt][0] + bb.x, acc[mt][nt][1] + bb.y);
            float2 v1 = make_float2(acc[mt][nt][2] + bb.x, acc[mt][nt][3] + bb.y);
            *(float2*)&C[m * DD + n]       = v0;
            *(float2*)&C[(m + 8) * DD + n] = v1;
        }
    }
}

// Q/K/V projections only (R projection deferred to overlap the proj phase)
__global__ void __launch_bounds__(128, 2) k_gemm_qkv(
    const float* __restrict__ x,
    const float* Wq, const float* bq,
    const float* Wk, const float* bk,
    const float* Wv, const float* bv)
{
    const float* W; const float* bias; float* C;
    switch (blockIdx.z) {
        case 0:  W = Wq; bias = bq; C = g_q; break;
        case 1:  W = Wk; bias = bk; C = g_k; break;
        default: W = Wv; bias = bv; C = g_v; break;
    }
    gemm_mma(x, W, bias, C);
}

// proj (att@Wo) and r (x@Wr) fused in one launch — fills the half-idle
// proj phase with the independent r work.
__global__ void __launch_bounds__(128, 2) k_gemm_pr(
    const float* __restrict__ x,
    const float* Wo, const float* bo,
    const float* Wr, const float* br)
{
    if (blockIdx.z == 0) gemm_mma(g_att, Wo, bo, g_proj);
    else                 gemm_mma(x,     Wr, br, g_r);
}

// ===========================================================================
// Local windowed attention: 4 queries per warp — K/V rows of the 67-key
// union window loaded ONCE per warp (3.7x fewer LDG). 4 warps (16 queries)
// per 128-thread block, grid 256.
// ===========================================================================
#define QPW 4                   // queries per warp
#define UW  (WW + QPW - 1)      // 67-key union window

__global__ void __launch_bounds__(128) k_attn()
{
    const int warp = threadIdx.x >> 5;
    const int lane = threadIdx.x & 31;
    const int q0   = blockIdx.x * 16 + warp * QPW;   // first query of this warp
    const int b    = q0 / SS;
    const int s0   = q0 - b * SS;
    const int base = b * SS;

    // 4 query rows in registers
    float4 qreg[QPW][4];
#pragma unroll
    for (int qi = 0; qi < QPW; qi++) {
        const float4* qrow = (const float4*)(g_q + (q0 + qi) * DD);
#pragma unroll
        for (int i = 0; i < 4; i++) qreg[qi][i] = qrow[lane + 32 * i];
    }

    __shared__ float sh[4][QPW][WW];
    const float scale = 0.044194173824159216f;   // 1/sqrt(512)

    // Score pass over union window: jg = s0-63+w, w = 0..66
    for (int w = 0; w < UW; w++) {
        const int jg = s0 - (WW - 1) + w;
        int jc = jg < 0 ? 0 : jg;
        const float4* krow = (const float4*)(g_k + (base + jc) * DD);
        float4 kv[4];
#pragma unroll
        for (int i = 0; i < 4; i++) kv[i] = krow[lane + 32 * i];

#pragma unroll
        for (int qi = 0; qi < QPW; qi++) {
            const unsigned wp = (unsigned)(w - qi);
            if (wp >= (unsigned)WW) continue;   // outside this query's window
            float part = 0.f;
#pragma unroll
            for (int i = 0; i < 4; i++)
                part += qreg[qi][i].x * kv[i].x + qreg[qi][i].y * kv[i].y
                      + qreg[qi][i].z * kv[i].z + qreg[qi][i].w * kv[i].w;
#pragma unroll
            for (int off = 16; off; off >>= 1)
                part += __shfl_down_sync(0xffffffffu, part, off);
            if (lane == 0)
                sh[warp][qi][wp] = (jg >= 0) ? part * scale : -1e9f;
        }
    }
    __syncwarp();

    // softmax per query (2 scores per lane)
#pragma unroll
    for (int qi = 0; qi < QPW; qi++) {
        float v0 = sh[warp][qi][lane], v1 = sh[warp][qi][lane + 32];
        float mx = fmaxf(v0, v1);
#pragma unroll
        for (int off = 16; off; off >>= 1)
            mx = fmaxf(mx, __shfl_xor_sync(0xffffffffu, mx, off));
        float e0 = expf(v0 - mx), e1 = expf(v1 - mx);
        float sum = e0 + e1;
#pragma unroll
        for (int off = 16; off; off >>= 1)
            sum += __shfl_xor_sync(0xffffffffu, sum, off);
        const float inv = 1.0f / sum;
        sh[warp][qi][lane]      = e0 * inv;
        sh[warp][qi][lane + 32] = e1 * inv;
    }
    __syncwarp();

    // AV pass over union window (keys ascending per query, as before)
    float4 acc[QPW][4];
#pragma unroll
    for (int qi = 0; qi < QPW; qi++)
#pragma unroll
        for (int i = 0; i < 4; i++) acc[qi][i] = make_float4(0.f, 0.f, 0.f, 0.f);

    for (int w = 0; w < UW; w++) {
        const int jg = s0 - (WW - 1) + w;
        if (jg < 0) continue;                    // p would be 0 anyway
        const float4* vrow = (const float4*)(g_v + (base + jg) * DD);
        float4 vv[4];
#pragma unroll
        for (int i = 0; i < 4; i++) vv[i] = vrow[lane + 32 * i];

#pragma unroll
        for (int qi = 0; qi < QPW; qi++) {
            const unsigned wp = (unsigned)(w - qi);
            if (wp >= (unsigned)WW) continue;
            const float p = sh[warp][qi][wp];
#pragma unroll
            for (int i = 0; i < 4; i++) {
                acc[qi][i].x += p * vv[i].x; acc[qi][i].y += p * vv[i].y;
                acc[qi][i].z += p * vv[i].z; acc[qi][i].w += p * vv[i].w;
            }
        }
    }
#pragma unroll
    for (int qi = 0; qi < QPW; qi++) {
        float4* orow = (float4*)(g_att + (q0 + qi) * DD);
#pragma unroll
        for (int i = 0; i < 4; i++) orow[lane + 32 * i] = acc[qi][i];
    }
}

// ===========================================================================
// Dual LayerNorm + add + exact GELU. 2 rows per 256-thread block,
// 128 threads per row, float4 everywhere.
// ===========================================================================
__global__ void __launch_bounds__(256) k_ln_gelu(
    const float* __restrict__ gamma, const float* __restrict__ beta,
    float* __restrict__ out)
{
    const int t    = threadIdx.x;
    const int half = t >> 7;
    const int lt   = t & 127;
    const int row  = blockIdx.x * 2 + half;

    const float4 p4 = ((const float4*)(g_proj + row * DD))[lt];
    const float4 r4 = ((const float4*)(g_r    + row * DD))[lt];

    float sp  = p4.x + p4.y + p4.z + p4.w;
    float spp = p4.x*p4.x + p4.y*p4.y + p4.z*p4.z + p4.w*p4.w;
    float sr  = r4.x + r4.y + r4.z + r4.w;
    float srr = r4.x*r4.x + r4.y*r4.y + r4.z*r4.z + r4.w*r4.w;

    __shared__ float red[2][4][4];
#pragma unroll
    for (int off = 16; off; off >>= 1) {
        sp  += __shfl_xor_sync(0xffffffffu, sp,  off);
        spp += __shfl_xor_sync(0xffffffffu, spp, off);
        sr  += __shfl_xor_sync(0xffffffffu, sr,  off);
        srr += __shfl_xor_sync(0xffffffffu, srr, off);
    }
    const int lane = t & 31, w = (t >> 5) & 3;
    if (lane == 0) {
        red[half][w][0] = sp;  red[half][w][1] = spp;
        red[half][w][2] = sr;  red[half][w][3] = srr;
    }
    __syncthreads();
    float Sp = 0.f, Spp = 0.f, Sr = 0.f, Srr = 0.f;
#pragma unroll
    for (int i = 0; i < 4; i++) {
        Sp += red[half][i][0]; Spp += red[half][i][1];
        Sr += red[half][i][2]; Srr += red[half][i][3];
    }

    const float invD = 1.0f / (float)DD;
    const float mup = Sp * invD;
    const float ip  = rsqrtf(Spp * invD - mup * mup + 1e-5f);
    const float mur = Sr * invD;
    const float ir  = rsqrtf(Srr * invD - mur * mur + 1e-5f);

    const float4 ga = ((const float4*)gamma)[lt];
    const float4 be = ((const float4*)beta)[lt];

    float4 y;
    y.x = (p4.x - mup) * ip * ga.x + be.x + (r4.x - mur) * ir * ga.x + be.x;
    y.y = (p4.y - mup) * ip * ga.y + be.y + (r4.y - mur) * ir * ga.y + be.y;
    y.z = (p4.z - mup) * ip * ga.z + be.z + (r4.z - mur) * ir * ga.z + be.z;
    y.w = (p4.w - mup) * ip * ga.w + be.w + (r4.w - mur) * ir * ga.w + be.w;

    float4 o;
    o.x = y.x * normcdff(y.x);
    o.y = y.y * normcdff(y.y);
    o.z = y.z * normcdff(y.z);
    o.w = y.w * normcdff(y.w);
    ((float4*)(out + row * DD))[lt] = o;
}

// ===========================================================================
extern "C" void kernel_launch(void* const* d_in, const int* in_sizes, int n_in,
                              void* d_out, int out_size)
{
    const float* x     = (const float*)d_in[0];
    const float* Wq    = (const float*)d_in[1];
    const float* bq    = (const float*)d_in[2];
    const float* Wk    = (const float*)d_in[3];
    const float* bk    = (const float*)d_in[4];
    const float* Wv    = (const float*)d_in[5];
    const float* bv    = (const float*)d_in[6];
    const float* Wo    = (const float*)d_in[7];
    const float* bo    = (const float*)d_in[8];
    const float* Wr    = (const float*)d_in[9];
    const float* br    = (const float*)d_in[10];
    const float* gamma = (const float*)d_in[11];
    const float* beta  = (const float*)d_in[12];
    float* out = (float*)d_out;

    k_gemm_qkv<<<dim3(4, 32, 3), 128>>>(x, Wq, bq, Wk, bk, Wv, bv);

    k_attn<<<MR / 16, 128>>>();

    k_gemm_pr<<<dim3(4, 32, 2), 128>>>(x, Wo, bo, Wr, br);

    k_ln_gelu<<<MR / 2, 256>>>(gamma, beta, out);
}

// round 15
// speedup vs baseline: 1.1686x; 1.1686x over previous
#include <cuda_runtime.h>
#include <math.h>
#include <stdint.h>

#define BB   2
#define SS   2048
#define DD   512
#define WW   64
#define MR   (BB*SS)     // 4096 rows

// Scratch (device globals — no allocation allowed)
__device__ float g_q[MR*DD];
__device__ float g_k[MR*DD];
__device__ float g_v[MR*DD];
__device__ float g_r[MR*DD];
__device__ float g_att[MR*DD];
__device__ float g_proj[MR*DD];

__device__ __forceinline__ uint32_t tf32r(float f) {
    uint32_t u; asm("cvt.rna.tf32.f32 %0, %1;" : "=r"(u) : "f"(f)); return u;
}

__device__ __forceinline__ void mma_tf32(float* c, const uint32_t* a, const uint32_t* b) {
    asm("mma.sync.aligned.m16n8k8.row.col.f32.tf32.tf32.f32 "
        "{%0,%1,%2,%3}, {%4,%5,%6,%7}, {%8,%9}, {%0,%1,%2,%3};"
        : "+f"(c[0]), "+f"(c[1]), "+f"(c[2]), "+f"(c[3])
        : "r"(a[0]), "r"(a[1]), "r"(a[2]), "r"(a[3]), "r"(b[0]), "r"(b[1]));
}

__device__ __forceinline__ void ldsm_x4(uint32_t* r, uint32_t addr) {
    asm volatile("ldmatrix.sync.aligned.m8n8.x4.shared.b16 {%0,%1,%2,%3}, [%4];"
                 : "=r"(r[0]), "=r"(r[1]), "=r"(r[2]), "=r"(r[3]) : "r"(addr));
}

// packed f32x2 FMA: d = a*b + d (two independent fp32 RN FMAs)
__device__ __forceinline__ void fma2(uint64_t& d, uint64_t a, uint64_t b) {
    asm("fma.rn.f32x2 %0, %1, %2, %0;" : "+l"(d) : "l"(a), "l"(b));
}
__device__ __forceinline__ uint64_t pack2(float lo, float hi) {
    uint64_t r;
    asm("mov.b64 %0, {%1, %2};" : "=l"(r) : "r"(__float_as_uint(lo)), "r"(__float_as_uint(hi)));
    return r;
}
__device__ __forceinline__ float2 unpack2(uint64_t v) {
    uint32_t lo, hi;
    asm("mov.b64 {%0, %1}, %2;" : "=r"(lo), "=r"(hi) : "l"(v));
    return make_float2(__uint_as_float(lo), __uint_as_float(hi));
}

// ===========================================================================
// tf32 tensor-core GEMM: C[4096,512] = A[4096,512] @ W[512,512] + bias
// CTA tile 128x128, BK=32, 128 threads (4 warps, warp tile 64x64).
// A fragments via ldmatrix.x4. (R13 body — best measured.)
// ===========================================================================
#define SKA 36
#define SKB 132

__device__ __forceinline__ void gemm_mma(const float* __restrict__ A,
                                         const float* __restrict__ W,
                                         const float* __restrict__ bias,
                                         float* __restrict__ C)
{
    __shared__ float As[128 * SKA];
    __shared__ float Bs[32 * SKB];

    const int tid  = threadIdx.x;
    const int lane = tid & 31;
    const int wid  = tid >> 5;
    const int g    = lane >> 2;
    const int tg   = lane & 3;
    const int m0   = blockIdx.y * 128;
    const int n0   = blockIdx.x * 128;
    const int wm   = (wid >> 1) * 64;
    const int wn   = (wid & 1) * 64;

    const int arow = tid >> 3;
    const int acol = (tid & 7) * 4;
    const int brow = tid >> 5;
    const int bcol = (tid & 31) * 4;

    const float* Ab = A + (m0 + arow) * DD + acol;
    const float* Wb = W + brow * DD + n0 + bcol;

    const uint32_t sAs = (uint32_t)__cvta_generic_to_shared(As);
    uint32_t ptrA[4];
#pragma unroll
    for (int mt = 0; mt < 4; mt++)
        ptrA[mt] = sAs + (((wm + mt * 16 + (lane & 15)) * SKA) + (lane >> 4) * 4) * 4;

    float4 pa[8], pb[8];
#pragma unroll
    for (int i = 0; i < 8; i++) {
        pa[i] = *(const float4*)(Ab + i * 16 * DD);
        pb[i] = *(const float4*)(Wb + i * 4 * DD);
    }

    float acc[4][8][4];
#pragma unroll
    for (int mt = 0; mt < 4; mt++)
#pragma unroll
        for (int nt = 0; nt < 8; nt++)
#pragma unroll
            for (int q = 0; q < 4; q++) acc[mt][nt][q] = 0.f;

    for (int ch = 0; ch < 16; ch++) {
        __syncthreads();
#pragma unroll
        for (int i = 0; i < 8; i++) {
            uint4 ua;
            ua.x = tf32r(pa[i].x); ua.y = tf32r(pa[i].y);
            ua.z = tf32r(pa[i].z); ua.w = tf32r(pa[i].w);
            *(uint4*)&As[(arow + 16 * i) * SKA + acol] = ua;
            uint4 ub;
            ub.x = tf32r(pb[i].x); ub.y = tf32r(pb[i].y);
            ub.z = tf32r(pb[i].z); ub.w = tf32r(pb[i].w);
            *(uint4*)&Bs[(brow + 4 * i) * SKB + bcol] = ub;
        }
        __syncthreads();

        if (ch < 15) {
            const float* Ab2 = Ab + (ch + 1) * 32;
            const float* Wb2 = Wb + (ch + 1) * 32 * DD;
#pragma unroll
            for (int i = 0; i < 8; i++) {
                pa[i] = *(const float4*)(Ab2 + i * 16 * DD);
                pb[i] = *(const float4*)(Wb2 + i * 4 * DD);
            }
        }

#pragma unroll
        for (int kk = 0; kk < 4; kk++) {
            const int kb = kk * 8;
            uint32_t af[4][4], bf[8][2];
#pragma unroll
            for (int mt = 0; mt < 4; mt++)
                ldsm_x4(af[mt], ptrA[mt] + kb * 4);
#pragma unroll
            for (int nt = 0; nt < 8; nt++) {
                const int n = wn + nt * 8 + g;
                bf[nt][0] = __float_as_uint(Bs[(kb + tg) * SKB + n]);
                bf[nt][1] = __float_as_uint(Bs[(kb + tg + 4) * SKB + n]);
            }
#pragma unroll
            for (int mt = 0; mt < 4; mt++)
#pragma unroll
                for (int nt = 0; nt < 8; nt++)
                    mma_tf32(acc[mt][nt], af[mt], bf[nt]);
        }
    }

#pragma unroll
    for (int nt = 0; nt < 8; nt++) {
        const int n = n0 + wn + nt * 8 + 2 * tg;
        const float2 bb = *(const float2*)&bias[n];
#pragma unroll
        for (int mt = 0; mt < 4; mt++) {
            const int m = m0 + wm + mt * 16 + g;
            float2 v0 = make_float2(acc[mt][nt][0] + bb.x, acc[mt][nt][1] + bb.y);
            float2 v1 = make_float2(acc[mt][nt][2] + bb.x, acc[mt][nt][3] + bb.y);
            *(float2*)&C[m * DD + n]       = v0;
            *(float2*)&C[(m + 8) * DD + n] = v1;
        }
    }
}

// Q/K/V projections only (R projection deferred to overlap the proj phase)
__global__ void __launch_bounds__(128, 2) k_gemm_qkv(
    const float* __restrict__ x,
    const float* Wq, const float* bq,
    const float* Wk, const float* bk,
    const float* Wv, const float* bv)
{
    const float* W; const float* bias; float* C;
    switch (blockIdx.z) {
        case 0:  W = Wq; bias = bq; C = g_q; break;
        case 1:  W = Wk; bias = bk; C = g_k; break;
        default: W = Wv; bias = bv; C = g_v; break;
    }
    gemm_mma(x, W, bias, C);
}

// proj (att@Wo) and r (x@Wr) fused in one launch — fills the half-idle
// proj phase with the independent r work.
__global__ void __launch_bounds__(128, 2) k_gemm_pr(
    const float* __restrict__ x,
    const float* Wo, const float* bo,
    const float* Wr, const float* br)
{
    if (blockIdx.z == 0) gemm_mma(g_att, Wo, bo, g_proj);
    else                 gemm_mma(x,     Wr, br, g_r);
}

// ===========================================================================
// Local windowed attention: one warp per query, 32 warps (1024 thr) per block.
// Packed f32x2 FMAs (FFMA2) halve issue count in score + AV passes.
// AV accumulation order identical to the scalar version (per-component).
// ===========================================================================
__global__ void __launch_bounds__(1024) k_attn()
{
    const int warp = threadIdx.x >> 5;
    const int lane = threadIdx.x & 31;
    const int gq   = blockIdx.x * 32 + warp;
    const int b    = gq / SS;
    const int s    = gq - b * SS;
    const int base = b * SS;

    // q row: 4 x 16B per lane, viewed as packed f32x2 pairs
    const ulonglong2* qrow = (const ulonglong2*)(g_q + gq * DD);
    ulonglong2 q2[4];
#pragma unroll
    for (int i = 0; i < 4; i++) q2[i] = qrow[lane + 32 * i];

    __shared__ float sh[32][WW];
    const int j0 = s - (WW - 1);
    const float scale = 0.044194173824159216f;   // 1/sqrt(512)

    // score pass
    for (int w = 0; w < WW; w++) {
        const int j = j0 + w;
        float part = 0.f;
        if (j >= 0) {
            const ulonglong2* krow = (const ulonglong2*)(g_k + (base + j) * DD);
            uint64_t a0 = 0, a1 = 0;
#pragma unroll
            for (int i = 0; i < 4; i++) {
                const ulonglong2 kv = krow[lane + 32 * i];
                fma2(a0, q2[i].x, kv.x);
                fma2(a1, q2[i].y, kv.y);
            }
            const float2 f0 = unpack2(a0), f1 = unpack2(a1);
            part = (f0.x + f0.y) + (f1.x + f1.y);
        }
#pragma unroll
        for (int off = 16; off; off >>= 1)
            part += __shfl_down_sync(0xffffffffu, part, off);
        if (lane == 0) sh[warp][w] = (j >= 0) ? part * scale : -1e9f;
    }
    __syncwarp();

    // softmax over 64 (2 scores per lane)
    float s0 = sh[warp][lane], s1 = sh[warp][lane + 32];
    float mx = fmaxf(s0, s1);
#pragma unroll
    for (int off = 16; off; off >>= 1)
        mx = fmaxf(mx, __shfl_xor_sync(0xffffffffu, mx, off));
    float e0 = expf(s0 - mx), e1 = expf(s1 - mx);
    float sum = e0 + e1;
#pragma unroll
    for (int off = 16; off; off >>= 1)
        sum += __shfl_xor_sync(0xffffffffu, sum, off);
    const float inv = 1.0f / sum;
    sh[warp][lane]      = e0 * inv;
    sh[warp][lane + 32] = e1 * inv;
    __syncwarp();

    // AV pass: 8 packed accumulators = 4 float4 (per-component, order as scalar)
    uint64_t av[8];
#pragma unroll
    for (int i = 0; i < 8; i++) av[i] = 0;

    for (int w = 0; w < WW; w++) {
        const int j = j0 + w;
        if (j < 0) continue;
        const float p = sh[warp][w];
        const uint64_t p2 = pack2(p, p);
        const ulonglong2* vrow = (const ulonglong2*)(g_v + (base + j) * DD);
#pragma unroll
        for (int i = 0; i < 4; i++) {
            const ulonglong2 vv = vrow[lane + 32 * i];
            fma2(av[2 * i],     vv.x, p2);
            fma2(av[2 * i + 1], vv.y, p2);
        }
    }
    ulonglong2* orow = (ulonglong2*)(g_att + gq * DD);
#pragma unroll
    for (int i = 0; i < 4; i++) {
        ulonglong2 o; o.x = av[2 * i]; o.y = av[2 * i + 1];
        orow[lane + 32 * i] = o;
    }
}

// ===========================================================================
// Dual LayerNorm + add + exact GELU. 2 rows per 256-thread block,
// 128 threads per row, float4 everywhere.
// ===========================================================================
__global__ void __launch_bounds__(256) k_ln_gelu(
    const float* __restrict__ gamma, const float* __restrict__ beta,
    float* __restrict__ out)
{
    const int t    = threadIdx.x;
    const int half = t >> 7;
    const int lt   = t & 127;
    const int row  = blockIdx.x * 2 + half;

    const float4 p4 = ((const float4*)(g_proj + row * DD))[lt];
    const float4 r4 = ((const float4*)(g_r    + row * DD))[lt];

    float sp  = p4.x + p4.y + p4.z + p4.w;
    float spp = p4.x*p4.x + p4.y*p4.y + p4.z*p4.z + p4.w*p4.w;
    float sr  = r4.x + r4.y + r4.z + r4.w;
    float srr = r4.x*r4.x + r4.y*r4.y + r4.z*r4.z + r4.w*r4.w;

    __shared__ float red[2][4][4];
#pragma unroll
    for (int off = 16; off; off >>= 1) {
        sp  += __shfl_xor_sync(0xffffffffu, sp,  off);
        spp += __shfl_xor_sync(0xffffffffu, spp, off);
        sr  += __shfl_xor_sync(0xffffffffu, sr,  off);
        srr += __shfl_xor_sync(0xffffffffu, srr, off);
    }
    const int lane = t & 31, w = (t >> 5) & 3;
    if (lane == 0) {
        red[half][w][0] = sp;  red[half][w][1] = spp;
        red[half][w][2] = sr;  red[half][w][3] = srr;
    }
    __syncthreads();
    float Sp = 0.f, Spp = 0.f, Sr = 0.f, Srr = 0.f;
#pragma unroll
    for (int i = 0; i < 4; i++) {
        Sp += red[half][i][0]; Spp += red[half][i][1];
        Sr += red[half][i][2]; Srr += red[half][i][3];
    }

    const float invD = 1.0f / (float)DD;
    const float mup = Sp * invD;
    const float ip  = rsqrtf(Spp * invD - mup * mup + 1e-5f);
    const float mur = Sr * invD;
    const float ir  = rsqrtf(Srr * invD - mur * mur + 1e-5f);

    const float4 ga = ((const float4*)gamma)[lt];
    const float4 be = ((const float4*)beta)[lt];

    float4 y;
    y.x = (p4.x - mup) * ip * ga.x + be.x + (r4.x - mur) * ir * ga.x + be.x;
    y.y = (p4.y - mup) * ip * ga.y + be.y + (r4.y - mur) * ir * ga.y + be.y;
    y.z = (p4.z - mup) * ip * ga.z + be.z + (r4.z - mur) * ir * ga.z + be.z;
    y.w = (p4.w - mup) * ip * ga.w + be.w + (r4.w - mur) * ir * ga.w + be.w;

    float4 o;
    o.x = y.x * normcdff(y.x);
    o.y = y.y * normcdff(y.y);
    o.z = y.z * normcdff(y.z);
    o.w = y.w * normcdff(y.w);
    ((float4*)(out + row * DD))[lt] = o;
}

// ===========================================================================
extern "C" void kernel_launch(void* const* d_in, const int* in_sizes, int n_in,
                              void* d_out, int out_size)
{
    const float* x     = (const float*)d_in[0];
    const float* Wq    = (const float*)d_in[1];
    const float* bq    = (const float*)d_in[2];
    const float* Wk    = (const float*)d_in[3];
    const float* bk    = (const float*)d_in[4];
    const float* Wv    = (const float*)d_in[5];
    const float* bv    = (const float*)d_in[6];
    const float* Wo    = (const float*)d_in[7];
    const float* bo    = (const float*)d_in[8];
    const float* Wr    = (const float*)d_in[9];
    const float* br    = (const float*)d_in[10];
    const float* gamma = (const float*)d_in[11];
    const float* beta  = (const float*)d_in[12];
    float* out = (float*)d_out;

    k_gemm_qkv<<<dim3(4, 32, 3), 128>>>(x, Wq, bq, Wk, bk, Wv, bv);

    k_attn<<<MR / 32, 1024>>>();

    k_gemm_pr<<<dim3(4, 32, 2), 128>>>(x, Wo, bo, Wr, br);

    k_ln_gelu<<<MR / 2, 256>>>(gamma, beta, out);
}

// round 16
// speedup vs baseline: 1.2012x; 1.0279x over previous
#include <cuda_runtime.h>
#include <math.h>
#include <stdint.h>

#define BB   2
#define SS   2048
#define DD   512
#define WW   64
#define MR   (BB*SS)     // 4096 rows

// Scratch (device globals — no allocation allowed)
__device__ float g_q[MR*DD];
__device__ float g_k[MR*DD];
__device__ float g_v[MR*DD];
__device__ float g_r[MR*DD];
__device__ float g_att[MR*DD];
__device__ float g_proj[MR*DD];

__device__ __forceinline__ uint32_t tf32r(float f) {
    uint32_t u; asm("cvt.rna.tf32.f32 %0, %1;" : "=r"(u) : "f"(f)); return u;
}

__device__ __forceinline__ void mma_tf32(float* c, const uint32_t* a, const uint32_t* b) {
    asm("mma.sync.aligned.m16n8k8.row.col.f32.tf32.tf32.f32 "
        "{%0,%1,%2,%3}, {%4,%5,%6,%7}, {%8,%9}, {%0,%1,%2,%3};"
        : "+f"(c[0]), "+f"(c[1]), "+f"(c[2]), "+f"(c[3])
        : "r"(a[0]), "r"(a[1]), "r"(a[2]), "r"(a[3]), "r"(b[0]), "r"(b[1]));
}

__device__ __forceinline__ void ldsm_x4(uint32_t* r, uint32_t addr) {
    asm volatile("ldmatrix.sync.aligned.m8n8.x4.shared.b16 {%0,%1,%2,%3}, [%4];"
                 : "=r"(r[0]), "=r"(r[1]), "=r"(r[2]), "=r"(r[3]) : "r"(addr));
}

// packed f32x2 FMA: d = a*b + d (two independent fp32 RN FMAs)
__device__ __forceinline__ void fma2(uint64_t& d, uint64_t a, uint64_t b) {
    asm("fma.rn.f32x2 %0, %1, %2, %0;" : "+l"(d) : "l"(a), "l"(b));
}
__device__ __forceinline__ uint64_t pack2(float lo, float hi) {
    uint64_t r;
    asm("mov.b64 %0, {%1, %2};" : "=l"(r) : "r"(__float_as_uint(lo)), "r"(__float_as_uint(hi)));
    return r;
}
__device__ __forceinline__ float2 unpack2(uint64_t v) {
    uint32_t lo, hi;
    asm("mov.b64 {%0, %1}, %2;" : "=r"(lo), "=r"(hi) : "l"(v));
    return make_float2(__uint_as_float(lo), __uint_as_float(hi));
}

// ===========================================================================
// tf32 tensor-core GEMM: C[4096,512] = A[4096,512] @ W[512,512] + bias
// CTA tile 128x128, BK=32, 128 threads (4 warps, warp tile 64x64).
// A fragments via ldmatrix.x4. (R13 body — best measured, ~92% of HMMA floor.)
// ===========================================================================
#define SKA 36
#define SKB 132

__device__ __forceinline__ void gemm_mma(const float* __restrict__ A,
                                         const float* __restrict__ W,
                                         const float* __restrict__ bias,
                                         float* __restrict__ C)
{
    __shared__ float As[128 * SKA];
    __shared__ float Bs[32 * SKB];

    const int tid  = threadIdx.x;
    const int lane = tid & 31;
    const int wid  = tid >> 5;
    const int g    = lane >> 2;
    const int tg   = lane & 3;
    const int m0   = blockIdx.y * 128;
    const int n0   = blockIdx.x * 128;
    const int wm   = (wid >> 1) * 64;
    const int wn   = (wid & 1) * 64;

    const int arow = tid >> 3;
    const int acol = (tid & 7) * 4;
    const int brow = tid >> 5;
    const int bcol = (tid & 31) * 4;

    const float* Ab = A + (m0 + arow) * DD + acol;
    const float* Wb = W + brow * DD + n0 + bcol;

    const uint32_t sAs = (uint32_t)__cvta_generic_to_shared(As);
    uint32_t ptrA[4];
#pragma unroll
    for (int mt = 0; mt < 4; mt++)
        ptrA[mt] = sAs + (((wm + mt * 16 + (lane & 15)) * SKA) + (lane >> 4) * 4) * 4;

    float4 pa[8], pb[8];
#pragma unroll
    for (int i = 0; i < 8; i++) {
        pa[i] = *(const float4*)(Ab + i * 16 * DD);
        pb[i] = *(const float4*)(Wb + i * 4 * DD);
    }

    float acc[4][8][4];
#pragma unroll
    for (int mt = 0; mt < 4; mt++)
#pragma unroll
        for (int nt = 0; nt < 8; nt++)
#pragma unroll
            for (int q = 0; q < 4; q++) acc[mt][nt][q] = 0.f;

    for (int ch = 0; ch < 16; ch++) {
        __syncthreads();
#pragma unroll
        for (int i = 0; i < 8; i++) {
            uint4 ua;
            ua.x = tf32r(pa[i].x); ua.y = tf32r(pa[i].y);
            ua.z = tf32r(pa[i].z); ua.w = tf32r(pa[i].w);
            *(uint4*)&As[(arow + 16 * i) * SKA + acol] = ua;
            uint4 ub;
            ub.x = tf32r(pb[i].x); ub.y = tf32r(pb[i].y);
            ub.z = tf32r(pb[i].z); ub.w = tf32r(pb[i].w);
            *(uint4*)&Bs[(brow + 4 * i) * SKB + bcol] = ub;
        }
        __syncthreads();

        if (ch < 15) {
            const float* Ab2 = Ab + (ch + 1) * 32;
            const float* Wb2 = Wb + (ch + 1) * 32 * DD;
#pragma unroll
            for (int i = 0; i < 8; i++) {
                pa[i] = *(const float4*)(Ab2 + i * 16 * DD);
                pb[i] = *(const float4*)(Wb2 + i * 4 * DD);
            }
        }

#pragma unroll
        for (int kk = 0; kk < 4; kk++) {
            const int kb = kk * 8;
            uint32_t af[4][4], bf[8][2];
#pragma unroll
            for (int mt = 0; mt < 4; mt++)
                ldsm_x4(af[mt], ptrA[mt] + kb * 4);
#pragma unroll
            for (int nt = 0; nt < 8; nt++) {
                const int n = wn + nt * 8 + g;
                bf[nt][0] = __float_as_uint(Bs[(kb + tg) * SKB + n]);
                bf[nt][1] = __float_as_uint(Bs[(kb + tg + 4) * SKB + n]);
            }
#pragma unroll
            for (int mt = 0; mt < 4; mt++)
#pragma unroll
                for (int nt = 0; nt < 8; nt++)
                    mma_tf32(acc[mt][nt], af[mt], bf[nt]);
        }
    }

#pragma unroll
    for (int nt = 0; nt < 8; nt++) {
        const int n = n0 + wn + nt * 8 + 2 * tg;
        const float2 bb = *(const float2*)&bias[n];
#pragma unroll
        for (int mt = 0; mt < 4; mt++) {
            const int m = m0 + wm + mt * 16 + g;
            float2 v0 = make_float2(acc[mt][nt][0] + bb.x, acc[mt][nt][1] + bb.y);
            float2 v1 = make_float2(acc[mt][nt][2] + bb.x, acc[mt][nt][3] + bb.y);
            *(float2*)&C[m * DD + n]       = v0;
            *(float2*)&C[(m + 8) * DD + n] = v1;
        }
    }
}

// Q/K/V projections only (R projection deferred to overlap the proj phase)
__global__ void __launch_bounds__(128, 2) k_gemm_qkv(
    const float* __restrict__ x,
    const float* Wq, const float* bq,
    const float* Wk, const float* bk,
    const float* Wv, const float* bv)
{
    const float* W; const float* bias; float* C;
    switch (blockIdx.z) {
        case 0:  W = Wq; bias = bq; C = g_q; break;
        case 1:  W = Wk; bias = bk; C = g_k; break;
        default: W = Wv; bias = bv; C = g_v; break;
    }
    gemm_mma(x, W, bias, C);
}

// proj (att@Wo) and r (x@Wr) fused in one launch — fills the half-idle
// proj phase with the independent r work.
__global__ void __launch_bounds__(128, 2) k_gemm_pr(
    const float* __restrict__ x,
    const float* Wo, const float* bo,
    const float* Wr, const float* br)
{
    if (blockIdx.z == 0) gemm_mma(g_att, Wo, bo, g_proj);
    else                 gemm_mma(x,     Wr, br, g_r);
}

// ===========================================================================
// Local windowed attention: one warp per query, 32 warps (1024 thr) per block.
// f32x2 packed FMAs; unroll-by-2 on score/AV loops to double LDG MLP.
// ===========================================================================
__global__ void __launch_bounds__(1024) k_attn()
{
    const int warp = threadIdx.x >> 5;
    const int lane = threadIdx.x & 31;
    const int gq   = blockIdx.x * 32 + warp;
    const int b    = gq / SS;
    const int s    = gq - b * SS;
    const int base = b * SS;

    const ulonglong2* qrow = (const ulonglong2*)(g_q + gq * DD);
    ulonglong2 q2[4];
#pragma unroll
    for (int i = 0; i < 4; i++) q2[i] = qrow[lane + 32 * i];

    __shared__ float sh[32][WW];
    const int j0 = s - (WW - 1);
    const float scale = 0.044194173824159216f;   // 1/sqrt(512)

    // score pass (unrolled x2 for memory-level parallelism)
#pragma unroll 2
    for (int w = 0; w < WW; w++) {
        const int j = j0 + w;
        float part = 0.f;
        if (j >= 0) {
            const ulonglong2* krow = (const ulonglong2*)(g_k + (base + j) * DD);
            ulonglong2 kv[4];
#pragma unroll
            for (int i = 0; i < 4; i++) kv[i] = krow[lane + 32 * i];
            uint64_t a0 = 0, a1 = 0;
#pragma unroll
            for (int i = 0; i < 4; i++) {
                fma2(a0, q2[i].x, kv[i].x);
                fma2(a1, q2[i].y, kv[i].y);
            }
            const float2 f0 = unpack2(a0), f1 = unpack2(a1);
            part = (f0.x + f0.y) + (f1.x + f1.y);
        }
#pragma unroll
        for (int off = 16; off; off >>= 1)
            part += __shfl_down_sync(0xffffffffu, part, off);
        if (lane == 0) sh[warp][w] = (j >= 0) ? part * scale : -1e9f;
    }
    __syncwarp();

    // softmax over 64 (2 scores per lane)
    float s0 = sh[warp][lane], s1 = sh[warp][lane + 32];
    float mx = fmaxf(s0, s1);
#pragma unroll
    for (int off = 16; off; off >>= 1)
        mx = fmaxf(mx, __shfl_xor_sync(0xffffffffu, mx, off));
    float e0 = expf(s0 - mx), e1 = expf(s1 - mx);
    float sum = e0 + e1;
#pragma unroll
    for (int off = 16; off; off >>= 1)
        sum += __shfl_xor_sync(0xffffffffu, sum, off);
    const float inv = 1.0f / sum;
    sh[warp][lane]      = e0 * inv;
    sh[warp][lane + 32] = e1 * inv;
    __syncwarp();

    // AV pass (unrolled x2)
    uint64_t av[8];
#pragma unroll
    for (int i = 0; i < 8; i++) av[i] = 0;

#pragma unroll 2
    for (int w = 0; w < WW; w++) {
        const int j = j0 + w;
        if (j < 0) continue;
        const float p = sh[warp][w];
        const uint64_t p2 = pack2(p, p);
        const ulonglong2* vrow = (const ulonglong2*)(g_v + (base + j) * DD);
        ulonglong2 vv[4];
#pragma unroll
        for (int i = 0; i < 4; i++) vv[i] = vrow[lane + 32 * i];
#pragma unroll
        for (int i = 0; i < 4; i++) {
            fma2(av[2 * i],     vv[i].x, p2);
            fma2(av[2 * i + 1], vv[i].y, p2);
        }
    }
    ulonglong2* orow = (ulonglong2*)(g_att + gq * DD);
#pragma unroll
    for (int i = 0; i < 4; i++) {
        ulonglong2 o; o.x = av[2 * i]; o.y = av[2 * i + 1];
        orow[lane + 32 * i] = o;
    }
}

// ===========================================================================
// Dual LayerNorm + add + exact GELU. One WARP per row (shfl-only reduction,
// no smem round trip, no __syncthreads). 8 rows per 256-thread block.
// ===========================================================================
__global__ void __launch_bounds__(256) k_ln_gelu(
    const float* __restrict__ gamma, const float* __restrict__ beta,
    float* __restrict__ out)
{
    const int lane = threadIdx.x & 31;
    const int wrp  = threadIdx.x >> 5;
    const int row  = blockIdx.x * 8 + wrp;

    const float4* prow = (const float4*)(g_proj + row * DD);
    const float4* rrow = (const float4*)(g_r    + row * DD);

    float4 p4[4], r4[4];
#pragma unroll
    for (int i = 0; i < 4; i++) {
        p4[i] = prow[lane + 32 * i];
        r4[i] = rrow[lane + 32 * i];
    }

    float sp = 0.f, spp = 0.f, sr = 0.f, srr = 0.f;
#pragma unroll
    for (int i = 0; i < 4; i++) {
        sp  += p4[i].x + p4[i].y + p4[i].z + p4[i].w;
        spp += p4[i].x*p4[i].x + p4[i].y*p4[i].y + p4[i].z*p4[i].z + p4[i].w*p4[i].w;
        sr  += r4[i].x + r4[i].y + r4[i].z + r4[i].w;
        srr += r4[i].x*r4[i].x + r4[i].y*r4[i].y + r4[i].z*r4[i].z + r4[i].w*r4[i].w;
    }
#pragma unroll
    for (int off = 16; off; off >>= 1) {
        sp  += __shfl_xor_sync(0xffffffffu, sp,  off);
        spp += __shfl_xor_sync(0xffffffffu, spp, off);
        sr  += __shfl_xor_sync(0xffffffffu, sr,  off);
        srr += __shfl_xor_sync(0xffffffffu, srr, off);
    }

    const float invD = 1.0f / (float)DD;
    const float mup = sp * invD;
    const float ip  = rsqrtf(spp * invD - mup * mup + 1e-5f);
    const float mur = sr * invD;
    const float ir  = rsqrtf(srr * invD - mur * mur + 1e-5f);

    float4* orow = (float4*)(out + row * DD);
#pragma unroll
    for (int i = 0; i < 4; i++) {
        const float4 ga = ((const float4*)gamma)[lane + 32 * i];
        const float4 be = ((const float4*)beta)[lane + 32 * i];
        float4 y;
        y.x = (p4[i].x - mup) * ip * ga.x + be.x + (r4[i].x - mur) * ir * ga.x + be.x;
        y.y = (p4[i].y - mup) * ip * ga.y + be.y + (r4[i].y - mur) * ir * ga.y + be.y;
        y.z = (p4[i].z - mup) * ip * ga.z + be.z + (r4[i].z - mur) * ir * ga.z + be.z;
        y.w = (p4[i].w - mup) * ip * ga.w + be.w + (r4[i].w - mur) * ir * ga.w + be.w;
        float4 o;
        o.x = y.x * normcdff(y.x);
        o.y = y.y * normcdff(y.y);
        o.z = y.z * normcdff(y.z);
        o.w = y.w * normcdff(y.w);
        orow[lane + 32 * i] = o;
    }
}

// ===========================================================================
extern "C" void kernel_launch(void* const* d_in, const int* in_sizes, int n_in,
                              void* d_out, int out_size)
{
    const float* x     = (const float*)d_in[0];
    const float* Wq    = (const float*)d_in[1];
    const float* bq    = (const float*)d_in[2];
    const float* Wk    = (const float*)d_in[3];
    const float* bk    = (const float*)d_in[4];
    const float* Wv    = (const float*)d_in[5];
    const float* bv    = (const float*)d_in[6];
    const float* Wo    = (const float*)d_in[7];
    const float* bo    = (const float*)d_in[8];
    const float* Wr    = (const float*)d_in[9];
    const float* br    = (const float*)d_in[10];
    const float* gamma = (const float*)d_in[11];
    const float* beta  = (const float*)d_in[12];
    float* out = (float*)d_out;

    k_gemm_qkv<<<dim3(4, 32, 3), 128>>>(x, Wq, bq, Wk, bk, Wv, bv);

    k_attn<<<MR / 32, 1024>>>();

    k_gemm_pr<<<dim3(4, 32, 2), 128>>>(x, Wo, bo, Wr, br);

    k_ln_gelu<<<MR / 8, 256>>>(gamma, beta, out);
}